// round 16
// baseline (speedup 1.0000x reference)
#include <cuda_runtime.h>
#include <cuda_bf16.h>
#include <math.h>

#define EPS 1e-5f

static const int F = 128;        // features (x is [N,128])
static const int F4 = 32;        // float4 per row
static const int GMAX = 1024;    // >= actual batch_size

// Scratch (no allocations allowed): __device__ globals.
// Zero-initialized at module load; finalize_kernel re-zeros s1/s2/cnt after
// consuming them, so every graph replay enters with zeroed accumulators.
__device__ float g_s1[GMAX * F];
__device__ float g_s2[GMAX * F];
__device__ float g_cnt[GMAX];
__device__ float g_a[GMAX * F];   // rstd * gamma
__device__ float g_b[GMAX * F];   // beta - mean * rstd * gamma

// ---------------------------------------------------------------------------
// 1) per-segment sum/sumsq (proven ~158us). batch sorted -> register
//    accumulation, flush on segment change. 512 threads = 4 row lanes x
//    128 features; 8 row-groups prefetched per iteration.
// ---------------------------------------------------------------------------
__global__ void __launch_bounds__(512) stats_kernel(
    const float* __restrict__ x, const int* __restrict__ batch,
    int N, int rows_per_block)
{
    const int f  = threadIdx.x & (F - 1);
    const int rl = threadIdx.x >> 7;

    const int row0    = blockIdx.x * rows_per_block;
    const int row_end = min(N, row0 + rows_per_block);
    if (row0 < N) {
        float s1 = 0.f, s2 = 0.f, cnt = 0.f;
        int cur = -1;

#define GN_FLUSH()                                                      \
        do {                                                            \
            if (cur >= 0) {                                             \
                atomicAdd(&g_s1[cur * F + f], s1);                      \
                atomicAdd(&g_s2[cur * F + f], s2);                      \
                if (f == 0) atomicAdd(&g_cnt[cur], cnt);                \
            }                                                           \
        } while (0)

#define GN_PROC(SEG, V)                                                 \
        do {                                                            \
            if ((SEG) != cur) {                                         \
                GN_FLUSH();                                             \
                cur = (SEG); s1 = 0.f; s2 = 0.f; cnt = 0.f;             \
            }                                                           \
            s1 += (V); s2 += (V) * (V); cnt += 1.f;                     \
        } while (0)

        int r = row0 + rl;
        for (; r + 28 < row_end; r += 32) {
            int   sg[8];
            float vv[8];
#pragma unroll
            for (int k = 0; k < 8; k++) sg[k] = __ldg(&batch[r + 4 * k]);
#pragma unroll
            for (int k = 0; k < 8; k++) vv[k] = __ldcs(&x[(size_t)(r + 4 * k) * F + f]);
#pragma unroll
            for (int k = 0; k < 8; k++) GN_PROC(sg[k], vv[k]);
        }
        for (; r < row_end; r += 4) {
            const int   seg = __ldg(&batch[r]);
            const float v   = __ldcs(&x[(size_t)r * F + f]);
            GN_PROC(seg, v);
        }
        GN_FLUSH();
#undef GN_PROC
#undef GN_FLUSH
    }
#if __CUDA_ARCH__ >= 900
    cudaTriggerProgrammaticLaunchCompletion();
#endif
}

// ---------------------------------------------------------------------------
// 2) finalize into fused affine tables (a = rstd*gamma, b = beta - mean*a),
//    then RE-ZERO s1/s2/cnt so the next graph replay starts clean (replaces
//    the dedicated zero kernel). idx ownership is exclusive per thread;
//    cnt[g] is only read by threads of one block -> sync then zero is safe.
// ---------------------------------------------------------------------------
__global__ void finalize_kernel(const float* __restrict__ gamma,
                                const float* __restrict__ beta,
                                const int* __restrict__ bs) {
#if __CUDA_ARCH__ >= 900
    cudaGridDependencySynchronize();   // wait for stats_kernel's atomics
#endif
    const int G = bs ? min(*bs, GMAX) : GMAX;
    const int idx = blockIdx.x * blockDim.x + threadIdx.x;
    const int g = idx >> 7;
    const int f = idx & (F - 1);
    if (idx < G * F) {
        const float cntv  = g_cnt[g];
        const float denom = fmaxf(cntv, 1.f);
        const float mean  = g_s1[idx] / denom;
        float var = g_s2[idx] / denom - mean * mean;
        var = fmaxf(var, EPS);
        const float rstd = rsqrtf(var + EPS);
        const float a = rstd * __ldg(&gamma[f]);
        g_a[idx] = a;
        g_b[idx] = __ldg(&beta[f]) - mean * a;
        // re-zero exclusively-owned accumulators
        g_s1[idx] = 0.f;
        g_s2[idx] = 0.f;
    }
    __syncthreads();                   // all reads of g_cnt[g] in this block done
    if (idx < G * F && f == 0) g_cnt[g] = 0.f;
#if __CUDA_ARCH__ >= 900
    cudaTriggerProgrammaticLaunchCompletion();
#endif
}

// ---------------------------------------------------------------------------
// 3) normalize (R12/R14 proven: grid-stride, 4x strided unroll, front-batched
//    loads, fused a/b tables -> 2 table loads + 1 FMA4 per element).
// ---------------------------------------------------------------------------
__global__ void __launch_bounds__(256) norm_kernel(
    const float4* __restrict__ x4, const int* __restrict__ batch,
    float4* __restrict__ out4, int total4)
{
#if __CUDA_ARCH__ >= 900
    cudaGridDependencySynchronize();   // wait for finalize's table writes
#endif
    const float4* __restrict__ a4 = (const float4*)g_a;
    const float4* __restrict__ b4 = (const float4*)g_b;

    const int stride = gridDim.x * blockDim.x;   // 4736*256 ≡ 0 mod 32
    const int c      = threadIdx.x & 31;         // invariant float4 column
    int i = blockIdx.x * blockDim.x + threadIdx.x;

    for (; i + 3 * stride < total4; i += 4 * stride) {
        const int iA = i, iB = i + stride, iC = i + 2 * stride, iD = i + 3 * stride;
        const int sA = __ldg(&batch[iA >> 5]);
        const int sB = __ldg(&batch[iB >> 5]);
        const int sC = __ldg(&batch[iC >> 5]);
        const int sD = __ldg(&batch[iD >> 5]);
        const float4 vA = __ldcs(&x4[iA]);
        const float4 vB = __ldcs(&x4[iB]);
        const float4 vC = __ldcs(&x4[iC]);
        const float4 vD = __ldcs(&x4[iD]);
        const float4 aA = __ldg(&a4[sA * F4 + c]);
        const float4 aB = __ldg(&a4[sB * F4 + c]);
        const float4 aC = __ldg(&a4[sC * F4 + c]);
        const float4 aD = __ldg(&a4[sD * F4 + c]);
        const float4 bA = __ldg(&b4[sA * F4 + c]);
        const float4 bB = __ldg(&b4[sB * F4 + c]);
        const float4 bC = __ldg(&b4[sC * F4 + c]);
        const float4 bD = __ldg(&b4[sD * F4 + c]);
        float4 o;
        o.x = vA.x * aA.x + bA.x;
        o.y = vA.y * aA.y + bA.y;
        o.z = vA.z * aA.z + bA.z;
        o.w = vA.w * aA.w + bA.w;
        __stcs(&out4[iA], o);
        o.x = vB.x * aB.x + bB.x;
        o.y = vB.y * aB.y + bB.y;
        o.z = vB.z * aB.z + bB.z;
        o.w = vB.w * aB.w + bB.w;
        __stcs(&out4[iB], o);
        o.x = vC.x * aC.x + bC.x;
        o.y = vC.y * aC.y + bC.y;
        o.z = vC.z * aC.z + bC.z;
        o.w = vC.w * aC.w + bC.w;
        __stcs(&out4[iC], o);
        o.x = vD.x * aD.x + bD.x;
        o.y = vD.y * aD.y + bD.y;
        o.z = vD.z * aD.z + bD.z;
        o.w = vD.w * aD.w + bD.w;
        __stcs(&out4[iD], o);
    }
    for (; i < total4; i += stride) {
        const int seg = __ldg(&batch[i >> 5]);
        const float4 v = __ldcs(&x4[i]);
        const float4 a = __ldg(&a4[seg * F4 + c]);
        const float4 b = __ldg(&b4[seg * F4 + c]);
        float4 o;
        o.x = v.x * a.x + b.x;
        o.y = v.y * a.y + b.y;
        o.z = v.z * a.z + b.z;
        o.w = v.w * a.w + b.w;
        __stcs(&out4[i], o);
    }
}

// ---------------------------------------------------------------------------
extern "C" void kernel_launch(void* const* d_in, const int* in_sizes, int n_in,
                              void* d_out, int out_size)
{
    const float* x     = (const float*)d_in[0];
    const float* gamma = (const float*)d_in[1];
    const float* beta  = (const float*)d_in[2];
    const int*   batch = (const int*)d_in[3];
    const int*   bs    = (n_in >= 5) ? (const int*)d_in[4] : nullptr;

    const int N = in_sizes[3];

    cudaLaunchAttribute pdl[1];
    pdl[0].id = cudaLaunchAttributeProgrammaticStreamSerialization;
    pdl[0].val.programmaticStreamSerializationAllowed = 1;

    // 1) stats (first node; accumulators pre-zeroed by previous launch /
    //    module load)
    {
        const int stat_blocks = 2368;       // 148 SMs * 16
        const int stat_rpb = (N + stat_blocks - 1) / stat_blocks;
        stats_kernel<<<stat_blocks, 512>>>(x, batch, N, stat_rpb);
    }

    // 2) finalize + re-zero (PDL after stats)
    {
        cudaLaunchConfig_t cfg = {};
        cfg.gridDim  = dim3((GMAX * F + 255) / 256);
        cfg.blockDim = dim3(256);
        cfg.attrs = pdl; cfg.numAttrs = 1;
        cudaLaunchKernelEx(&cfg, finalize_kernel, gamma, beta, bs);
    }

    // 3) normalize (PDL after finalize)
    {
        const int total4 = N * F4;
        const float4* x4 = (const float4*)x;
        float4* o4 = (float4*)d_out;
        cudaLaunchConfig_t cfg = {};
        cfg.gridDim  = dim3(4736);          // 148 SMs * 32
        cfg.blockDim = dim3(256);
        cfg.attrs = pdl; cfg.numAttrs = 1;
        cudaLaunchKernelEx(&cfg, norm_kernel, x4, batch, o4, total4);
    }
}

// round 17
// speedup vs baseline: 1.1935x; 1.1935x over previous
#include <cuda_runtime.h>
#include <cuda_bf16.h>
#include <math.h>

#define EPS 1e-5f

static const int F = 128;        // features (x is [N,128])
static const int F4 = 32;        // float4 per row
static const int GMAX = 1024;    // >= actual batch_size

// Scratch (no allocations allowed): __device__ globals.
__device__ float g_s1[GMAX * F];
__device__ float g_s2[GMAX * F];
__device__ float g_cnt[GMAX];
__device__ float g_a[GMAX * F];   // rstd * gamma
__device__ float g_b[GMAX * F];   // beta - mean * rstd * gamma

// ---------------------------------------------------------------------------
// 0) zero the accumulators (bounded by runtime batch_size)
// ---------------------------------------------------------------------------
__global__ void zero_kernel(const int* __restrict__ bs) {
    const int G = bs ? min(*bs, GMAX) : GMAX;
    const int total = 2 * G * F + G;
    for (int i = blockIdx.x * blockDim.x + threadIdx.x; i < total;
         i += gridDim.x * blockDim.x) {
        if (i < G * F)            g_s1[i] = 0.f;
        else if (i < 2 * G * F)   g_s2[i - G * F] = 0.f;
        else                      g_cnt[i - 2 * G * F] = 0.f;
    }
}

// ---------------------------------------------------------------------------
// 1) per-segment sum/sumsq. batch sorted -> register accumulation, flush on
//    segment change. 512 threads = 4 row lanes x 128 features; 8 row-groups
//    prefetched. FAST PATH: a thread's 8-row group (28-row span, segments
//    ~7800 rows) is almost always single-segment -> one compare per group
//    instead of 8 compare+branch chains (stats was 81% issue-bound).
// ---------------------------------------------------------------------------
__global__ void __launch_bounds__(512) stats_kernel(
    const float* __restrict__ x, const int* __restrict__ batch,
    int N, int rows_per_block)
{
    const int f  = threadIdx.x & (F - 1);
    const int rl = threadIdx.x >> 7;

    const int row0    = blockIdx.x * rows_per_block;
    const int row_end = min(N, row0 + rows_per_block);
    if (row0 >= N) return;

    float s1 = 0.f, s2 = 0.f, cnt = 0.f;
    int cur = -1;

#define GN_FLUSH()                                                      \
    do {                                                                \
        if (cur >= 0) {                                                 \
            atomicAdd(&g_s1[cur * F + f], s1);                          \
            atomicAdd(&g_s2[cur * F + f], s2);                          \
            if (f == 0) atomicAdd(&g_cnt[cur], cnt);                    \
        }                                                               \
    } while (0)

#define GN_PROC(SEG, V)                                                 \
    do {                                                                \
        if ((SEG) != cur) {                                             \
            GN_FLUSH();                                                 \
            cur = (SEG); s1 = 0.f; s2 = 0.f; cnt = 0.f;                 \
        }                                                               \
        s1 += (V); s2 += (V) * (V); cnt += 1.f;                         \
    } while (0)

    int r = row0 + rl;
    for (; r + 28 < row_end; r += 32) {
        int   sg[8];
        float vv[8];
#pragma unroll
        for (int k = 0; k < 8; k++) sg[k] = __ldg(&batch[r + 4 * k]);
#pragma unroll
        for (int k = 0; k < 8; k++) vv[k] = __ldcs(&x[(size_t)(r + 4 * k) * F + f]);
        if (sg[0] == cur && sg[7] == cur) {
            // uniform group in current segment: no per-element control flow
#pragma unroll
            for (int k = 0; k < 8; k++) { s1 += vv[k]; s2 += vv[k] * vv[k]; }
            cnt += 8.f;
        } else {
            // segment boundary inside (or first) group: exact slow path
#pragma unroll
            for (int k = 0; k < 8; k++) GN_PROC(sg[k], vv[k]);
        }
    }
    for (; r < row_end; r += 4) {
        const int   seg = __ldg(&batch[r]);
        const float v   = __ldcs(&x[(size_t)r * F + f]);
        GN_PROC(seg, v);
    }
    GN_FLUSH();
#undef GN_PROC
#undef GN_FLUSH
}

// ---------------------------------------------------------------------------
// 2) finalize into fused affine tables: a = rstd*gamma, b = beta - mean*a
// ---------------------------------------------------------------------------
__global__ void finalize_kernel(const float* __restrict__ gamma,
                                const float* __restrict__ beta,
                                const int* __restrict__ bs) {
    const int G = bs ? min(*bs, GMAX) : GMAX;
    int idx = blockIdx.x * blockDim.x + threadIdx.x;
    if (idx >= G * F) return;
    const int g = idx >> 7;
    const int f = idx & (F - 1);
    const float cntv  = g_cnt[g];
    const float denom = fmaxf(cntv, 1.f);
    const float mean  = g_s1[idx] / denom;
    float var = g_s2[idx] / denom - mean * mean;
    var = fmaxf(var, EPS);
    const float rstd = rsqrtf(var + EPS);
    const float a = rstd * __ldg(&gamma[f]);
    g_a[idx] = a;
    g_b[idx] = __ldg(&beta[f]) - mean * a;
}

// ---------------------------------------------------------------------------
// 3) normalize (R12 proven: grid-stride, 4x strided unroll, front-batched
//    loads, fused a/b tables -> 2 table loads + 1 FMA4 per element).
// ---------------------------------------------------------------------------
__global__ void __launch_bounds__(256) norm_kernel(
    const float4* __restrict__ x4, const int* __restrict__ batch,
    float4* __restrict__ out4, int total4)
{
    const float4* __restrict__ a4 = (const float4*)g_a;
    const float4* __restrict__ b4 = (const float4*)g_b;

    const int stride = gridDim.x * blockDim.x;   // 4736*256 ≡ 0 mod 32
    const int c      = threadIdx.x & 31;         // invariant float4 column
    int i = blockIdx.x * blockDim.x + threadIdx.x;

    for (; i + 3 * stride < total4; i += 4 * stride) {
        const int iA = i, iB = i + stride, iC = i + 2 * stride, iD = i + 3 * stride;
        const int sA = __ldg(&batch[iA >> 5]);
        const int sB = __ldg(&batch[iB >> 5]);
        const int sC = __ldg(&batch[iC >> 5]);
        const int sD = __ldg(&batch[iD >> 5]);
        const float4 vA = __ldcs(&x4[iA]);
        const float4 vB = __ldcs(&x4[iB]);
        const float4 vC = __ldcs(&x4[iC]);
        const float4 vD = __ldcs(&x4[iD]);
        const float4 aA = __ldg(&a4[sA * F4 + c]);
        const float4 aB = __ldg(&a4[sB * F4 + c]);
        const float4 aC = __ldg(&a4[sC * F4 + c]);
        const float4 aD = __ldg(&a4[sD * F4 + c]);
        const float4 bA = __ldg(&b4[sA * F4 + c]);
        const float4 bB = __ldg(&b4[sB * F4 + c]);
        const float4 bC = __ldg(&b4[sC * F4 + c]);
        const float4 bD = __ldg(&b4[sD * F4 + c]);
        float4 o;
        o.x = vA.x * aA.x + bA.x;
        o.y = vA.y * aA.y + bA.y;
        o.z = vA.z * aA.z + bA.z;
        o.w = vA.w * aA.w + bA.w;
        __stcs(&out4[iA], o);
        o.x = vB.x * aB.x + bB.x;
        o.y = vB.y * aB.y + bB.y;
        o.z = vB.z * aB.z + bB.z;
        o.w = vB.w * aB.w + bB.w;
        __stcs(&out4[iB], o);
        o.x = vC.x * aC.x + bC.x;
        o.y = vC.y * aC.y + bC.y;
        o.z = vC.z * aC.z + bC.z;
        o.w = vC.w * aC.w + bC.w;
        __stcs(&out4[iC], o);
        o.x = vD.x * aD.x + bD.x;
        o.y = vD.y * aD.y + bD.y;
        o.z = vD.z * aD.z + bD.z;
        o.w = vD.w * aD.w + bD.w;
        __stcs(&out4[iD], o);
    }
    for (; i < total4; i += stride) {
        const int seg = __ldg(&batch[i >> 5]);
        const float4 v = __ldcs(&x4[i]);
        const float4 a = __ldg(&a4[seg * F4 + c]);
        const float4 b = __ldg(&b4[seg * F4 + c]);
        float4 o;
        o.x = v.x * a.x + b.x;
        o.y = v.y * a.y + b.y;
        o.z = v.z * a.z + b.z;
        o.w = v.w * a.w + b.w;
        __stcs(&out4[i], o);
    }
}

// ---------------------------------------------------------------------------
extern "C" void kernel_launch(void* const* d_in, const int* in_sizes, int n_in,
                              void* d_out, int out_size)
{
    const float* x     = (const float*)d_in[0];
    const float* gamma = (const float*)d_in[1];
    const float* beta  = (const float*)d_in[2];
    const int*   batch = (const int*)d_in[3];
    const int*   bs    = (n_in >= 5) ? (const int*)d_in[4] : nullptr;

    const int N = in_sizes[3];

    zero_kernel<<<256, 256>>>(bs);

    const int stat_blocks = 2368;       // 148 SMs * 16
    const int stat_rpb = (N + stat_blocks - 1) / stat_blocks;
    stats_kernel<<<stat_blocks, 512>>>(x, batch, N, stat_rpb);

    finalize_kernel<<<(GMAX * F + 255) / 256, 256>>>(gamma, beta, bs);

    const int total4 = N * F4;
    const int norm_blocks = 4736;       // 148 SMs * 32
    norm_kernel<<<norm_blocks, 256>>>((const float4*)x, batch,
                                      (float4*)d_out, total4);
}